// round 8
// baseline (speedup 1.0000x reference)
#include <cuda_runtime.h>
#include <cuda_fp16.h>
#include <cstdint>

#define D_MODEL_C 1024
#define DK_C 64
#define B_C 4
#define S_C 4096
#define NROWS_C (B_C * S_C)
#define NSPLIT 4
#define KV_PER_SPLIT (S_C / NSPLIT)          // 1024
#define TILES_PER_SPLIT (KV_PER_SPLIT / 64)  // 16

// Scratch. Static device arrays: allocation-free.
__device__ float g_Q[NROWS_C * DK_C];
__device__ float g_K[NROWS_C * DK_C];
__device__ float g_V[NROWS_C * DK_C];
__device__ float g_Opart[NSPLIT * NROWS_C * DK_C];
__device__ float g_m[NSPLIT * NROWS_C];
__device__ float g_l[NSPLIT * NROWS_C];
__device__ __half g_Wh[192 * 1024];   // W transposed: [mat*64+col][k], fp16

static __device__ __forceinline__ uint32_t smem_to_u32(const void* p) {
    uint32_t a;
    asm("{ .reg .u64 t; cvta.to.shared.u64 t, %1; cvt.u32.u64 %0, t; }"
        : "=r"(a) : "l"(p));
    return a;
}
static __device__ __forceinline__ float exp2_approx(float x) {
    float y;
    asm("ex2.approx.f32 %0, %1;" : "=f"(y) : "f"(x));
    return y;
}
static __device__ __forceinline__ void ldsm_x4(uint32_t a[4], uint32_t addr) {
    asm volatile("ldmatrix.sync.aligned.m8n8.x4.shared.b16 {%0,%1,%2,%3}, [%4];"
        : "=r"(a[0]), "=r"(a[1]), "=r"(a[2]), "=r"(a[3]) : "r"(addr));
}
static __device__ __forceinline__ void ldsm_x4_t(uint32_t a[4], uint32_t addr) {
    asm volatile("ldmatrix.sync.aligned.m8n8.x4.trans.shared.b16 {%0,%1,%2,%3}, [%4];"
        : "=r"(a[0]), "=r"(a[1]), "=r"(a[2]), "=r"(a[3]) : "r"(addr));
}
static __device__ __forceinline__ void mma_f16(float c[4], const uint32_t a[4],
                                               uint32_t b0, uint32_t b1) {
    asm volatile(
        "mma.sync.aligned.m16n8k16.row.col.f32.f16.f16.f32 "
        "{%0,%1,%2,%3}, {%4,%5,%6,%7}, {%8,%9}, {%0,%1,%2,%3};"
        : "+f"(c[0]), "+f"(c[1]), "+f"(c[2]), "+f"(c[3])
        : "r"(a[0]), "r"(a[1]), "r"(a[2]), "r"(a[3]), "r"(b0), "r"(b1));
}
static __device__ __forceinline__ uint32_t pack_h2(float x, float y) {
    __half2 h = __floats2half2_rn(x, y);
    return *reinterpret_cast<uint32_t*>(&h);
}
static __device__ __forceinline__ uint4 cvt8_h(float4 v0, float4 v1) {
    return make_uint4(pack_h2(v0.x, v0.y), pack_h2(v0.z, v0.w),
                      pack_h2(v1.x, v1.y), pack_h2(v1.z, v1.w));
}

// ---------------------------------------------------------------------------
// Kernel 0: W -> K-major fp16.  g_Wh[(mat*64+n)][k] = W[k][n]
// ---------------------------------------------------------------------------
__global__ __launch_bounds__(256)
void wconv_kernel(const float* __restrict__ Wq, const float* __restrict__ Wk,
                  const float* __restrict__ Wv)
{
    int idx = blockIdx.x * 256 + threadIdx.x;   // 192*1024
    int n = idx >> 10;
    int k = idx & 1023;
    const float* W = (n < 64) ? Wq : (n < 128) ? Wk : Wv;
    g_Wh[(size_t)n * 1024 + k] = __float2half(W[(size_t)k * DK_C + (n & 63)]);
}

// ---------------------------------------------------------------------------
// Kernel 1: QKV projection, fp16 m16n8k16 + ldmatrix.
// Grid (128, 3). Block 256 (8 warps): warp = row-slab(32) x col-half(32).
// Es [128 rows][40 halves], Ws [64 cols][40 halves] (K-major, from g_Wh).
// ---------------------------------------------------------------------------
#define QKC 32
#define ESH 40    // halves; row stride 80B -> LDSM rows on banks 20i%32, distinct
#define WSH 40

__global__ __launch_bounds__(256)
void qkv_h_kernel(const float* __restrict__ emb,
                  const float* __restrict__ bq,
                  const float* __restrict__ bk,
                  const float* __restrict__ bv)
{
    __shared__ __align__(16) __half Es[128 * ESH];
    __shared__ __align__(16) __half Ws[64 * WSH];

    const int tid  = threadIdx.x;
    const int warp = tid >> 5;
    const int lane = tid & 31;
    const int rs   = warp & 3;
    const int ch   = warp >> 2;
    const int row0 = blockIdx.x * 128;
    const int mat  = blockIdx.y;

    const float* bias = (mat == 0) ? bq : (mat == 1) ? bk : bv;
    float* outp       = (mat == 0) ? g_Q : (mat == 1) ? g_K : g_V;

    float acc[2][4][4];
#pragma unroll
    for (int mt = 0; mt < 2; ++mt)
#pragma unroll
        for (int n = 0; n < 4; ++n)
#pragma unroll
            for (int j = 0; j < 4; ++j) acc[mt][n][j] = 0.f;

    const uint32_t esb = smem_to_u32(Es);
    const uint32_t wsb = smem_to_u32(Ws);
    const int l8 = lane & 7;
    // A-frag x4 lane pattern: m0 lanes0-7 (r+i,k0) | m1 8-15 (r+8+i,k0)
    //                         m2 16-23 (r+i,k0+8)  | m3 24-31 (r+8+i,k0+8)
    const int arow = l8 + ((lane >> 3) & 1) * 8;
    const int acol = ((lane >> 4) & 1) * 8;
    // B-frag x4 (K-major W): m0 (n+i,k0) | m1 (n+i,k0+8) | m2 (n+8+i,k0) | m3 (n+8+i,k0+8)
    const int brow = l8 + ((lane >> 4) & 1) * 8;
    const int bcol = ((lane >> 3) & 1) * 8;

    const int er = tid >> 2, ecg = tid & 3;     // Es loader: 128r x 4 groups, 2/thread
    const int wc = tid >> 2, wkg = tid & 3;     // Ws loader: 64c x 4 groups, 1/thread

    for (int kc = 0; kc < D_MODEL_C / QKC; ++kc) {
        __syncthreads();
#pragma unroll
        for (int i = 0; i < 2; ++i) {
            int idx = tid + i * 256;
            int r = idx >> 2, cg = idx & 3;
            const float* src = emb + (size_t)(row0 + r) * D_MODEL_C + kc * QKC + cg * 8;
            float4 v0 = *reinterpret_cast<const float4*>(src);
            float4 v1 = *reinterpret_cast<const float4*>(src + 4);
            *reinterpret_cast<uint4*>(&Es[r * ESH + cg * 8]) = cvt8_h(v0, v1);
        }
        {
            uint4 w = *reinterpret_cast<const uint4*>(
                &g_Wh[(size_t)(mat * 64 + wc) * 1024 + kc * QKC + wkg * 8]);
            *reinterpret_cast<uint4*>(&Ws[wc * WSH + wkg * 8]) = w;
        }
        __syncthreads();
#pragma unroll
        for (int ks = 0; ks < 2; ++ks) {
            uint32_t a[2][4];
#pragma unroll
            for (int mt = 0; mt < 2; ++mt) {
                uint32_t ad = esb + ((rs * 32 + mt * 16 + arow) * ESH + ks * 16 + acol) * 2;
                ldsm_x4(a[mt], ad);
            }
#pragma unroll
            for (int np = 0; np < 2; ++np) {
                uint32_t b[4];
                uint32_t bd = wsb + ((ch * 32 + np * 16 + brow) * WSH + ks * 16 + bcol) * 2;
                ldsm_x4(b, bd);
                mma_f16(acc[0][2 * np],     a[0], b[0], b[1]);
                mma_f16(acc[1][2 * np],     a[1], b[0], b[1]);
                mma_f16(acc[0][2 * np + 1], a[0], b[2], b[3]);
                mma_f16(acc[1][2 * np + 1], a[1], b[2], b[3]);
            }
        }
    }
    const int g  = lane >> 2;
    const int cb = (lane & 3) * 2;
#pragma unroll
    for (int mt = 0; mt < 2; ++mt) {
        const int r = row0 + rs * 32 + mt * 16 + g;
#pragma unroll
        for (int n = 0; n < 4; ++n) {
            int col = ch * 32 + n * 8 + cb;
            float b0 = bias[col], b1 = bias[col + 1];
            *reinterpret_cast<float2*>(&outp[(size_t)r * DK_C + col]) =
                make_float2(acc[mt][n][0] + b0, acc[mt][n][1] + b1);
            *reinterpret_cast<float2*>(&outp[(size_t)(r + 8) * DK_C + col]) =
                make_float2(acc[mt][n][2] + b0, acc[mt][n][3] + b1);
        }
    }
}

// ---------------------------------------------------------------------------
// Kernel 2: flash attention, fp16 m16n8k16 + ldmatrix, split-KV (4).
// Br=Bc=64, 4 warps. Kh/Vh/Ph fp16 tiles, stride 72 halves (144B rows).
// V B-frags via ldmatrix.trans (no transpose in loader).
// ---------------------------------------------------------------------------
#define ATS 72    // halves; 144B row stride -> LDSM rows on banks 4i%32, distinct

__global__ __launch_bounds__(128)
void attn_kernel()
{
    __shared__ __align__(16) unsigned char smema[3 * 64 * ATS * 2];
    __half* Kh = reinterpret_cast<__half*>(smema);
    __half* Vh = Kh + 64 * ATS;
    __half* Ph = Vh + 64 * ATS;
    float*  Qst = reinterpret_cast<float*>(smema);   // 16KB overlay on Kh+Vh

    const int tid   = threadIdx.x;
    const int warp  = tid >> 5;
    const int lane  = tid & 31;
    const int b     = blockIdx.y;
    const int q0    = blockIdx.x * 64;
    const int split = blockIdx.z;
    const int t0t   = split * TILES_PER_SPLIT;

    const float* Qg = g_Q + ((size_t)b * S_C + q0) * DK_C;
    const float* Kg = g_K + (size_t)b * S_C * DK_C;
    const float* Vg = g_V + (size_t)b * S_C * DK_C;

    // Stage Q fp32, build fp16 A-fragments in registers
#pragma unroll
    for (int i = 0; i < 8; ++i) {
        int id = tid + i * 128;
        int r = id >> 4, c4 = (id & 15) * 4;
        *reinterpret_cast<float4*>(&Qst[r * 64 + c4]) =
            *reinterpret_cast<const float4*>(&Qg[(size_t)r * DK_C + c4]);
    }
    __syncthreads();

    const int g  = lane >> 2;
    const int ac = lane & 3;
    const int ar = warp * 16 + g;
    const float qsc = 1.4426950408889634f * 0.125f;   // log2(e)/sqrt(dk)
    uint32_t qf[4][4];
#pragma unroll
    for (int ks = 0; ks < 4; ++ks) {
        int k0 = ks * 16 + 2 * ac;
        qf[ks][0] = pack_h2(Qst[ar * 64 + k0] * qsc,       Qst[ar * 64 + k0 + 1] * qsc);
        qf[ks][1] = pack_h2(Qst[(ar + 8) * 64 + k0] * qsc, Qst[(ar + 8) * 64 + k0 + 1] * qsc);
        qf[ks][2] = pack_h2(Qst[ar * 64 + k0 + 8] * qsc,   Qst[ar * 64 + k0 + 9] * qsc);
        qf[ks][3] = pack_h2(Qst[(ar + 8) * 64 + k0 + 8] * qsc, Qst[(ar + 8) * 64 + k0 + 9] * qsc);
    }

    const uint32_t kb = smem_to_u32(Kh);
    const uint32_t vb = smem_to_u32(Vh);
    const uint32_t pb = smem_to_u32(Ph);
    const int l8 = lane & 7;
    const int arow = l8 + ((lane >> 3) & 1) * 8;       // A pattern
    const int acol = ((lane >> 4) & 1) * 8;
    const int brow = l8 + ((lane >> 4) & 1) * 8;       // B (K-major) pattern
    const int bcol = ((lane >> 3) & 1) * 8;
    const int trow = l8 + ((lane >> 3) & 1) * 8;       // B-trans (V) pattern
    const int tcol = ((lane >> 4) & 1) * 8;

    float o[8][4];
#pragma unroll
    for (int n = 0; n < 8; ++n)
#pragma unroll
        for (int j = 0; j < 4; ++j) o[n][j] = 0.f;
    float m0 = -1e30f, m1 = -1e30f, l0 = 0.f, l1 = 0.f;

    for (int tt = 0; tt < TILES_PER_SPLIT; ++tt) {
        const int t = t0t + tt;
        __syncthreads();   // all warps done with Kh/Vh/Ph (and Qst on iter 0)
        const float* Kt = Kg + (size_t)t * 64 * DK_C;
        const float* Vt = Vg + (size_t)t * 64 * DK_C;
#pragma unroll
        for (int i = 0; i < 4; ++i) {
            int idx = tid + i * 128;
            int r = idx >> 3, cg = idx & 7;
            const float* ks_ = Kt + (size_t)r * DK_C + cg * 8;
            const float* vs_ = Vt + (size_t)r * DK_C + cg * 8;
            float4 k0v = *reinterpret_cast<const float4*>(ks_);
            float4 k1v = *reinterpret_cast<const float4*>(ks_ + 4);
            float4 v0v = *reinterpret_cast<const float4*>(vs_);
            float4 v1v = *reinterpret_cast<const float4*>(vs_ + 4);
            *reinterpret_cast<uint4*>(&Kh[r * ATS + cg * 8]) = cvt8_h(k0v, k1v);
            *reinterpret_cast<uint4*>(&Vh[r * ATS + cg * 8]) = cvt8_h(v0v, v1v);
        }
        __syncthreads();

        // S = Q @ K^T (log2-domain logits)
        float s[8][4];
#pragma unroll
        for (int n = 0; n < 8; ++n)
#pragma unroll
            for (int j = 0; j < 4; ++j) s[n][j] = 0.f;
#pragma unroll
        for (int ks = 0; ks < 4; ++ks) {
#pragma unroll
            for (int np = 0; np < 4; ++np) {
                uint32_t bfr[4];
                uint32_t bd = kb + ((np * 16 + brow) * ATS + ks * 16 + bcol) * 2;
                ldsm_x4(bfr, bd);
                mma_f16(s[2 * np],     qf[ks], bfr[0], bfr[1]);
                mma_f16(s[2 * np + 1], qf[ks], bfr[2], bfr[3]);
            }
        }

        // Online softmax
        float mx0 = m0, mx1 = m1;
#pragma unroll
        for (int n = 0; n < 8; ++n) {
            mx0 = fmaxf(mx0, fmaxf(s[n][0], s[n][1]));
            mx1 = fmaxf(mx1, fmaxf(s[n][2], s[n][3]));
        }
        mx0 = fmaxf(mx0, __shfl_xor_sync(0xffffffffu, mx0, 1));
        mx0 = fmaxf(mx0, __shfl_xor_sync(0xffffffffu, mx0, 2));
        mx1 = fmaxf(mx1, __shfl_xor_sync(0xffffffffu, mx1, 1));
        mx1 = fmaxf(mx1, __shfl_xor_sync(0xffffffffu, mx1, 2));
        float a0 = exp2_approx(m0 - mx0);
        float a1 = exp2_approx(m1 - mx1);
        float rs0 = 0.f, rs1 = 0.f;
#pragma unroll
        for (int n = 0; n < 8; ++n) {
            s[n][0] = exp2_approx(s[n][0] - mx0);
            s[n][1] = exp2_approx(s[n][1] - mx0);
            s[n][2] = exp2_approx(s[n][2] - mx1);
            s[n][3] = exp2_approx(s[n][3] - mx1);
            rs0 += s[n][0] + s[n][1];
            rs1 += s[n][2] + s[n][3];
        }
        rs0 += __shfl_xor_sync(0xffffffffu, rs0, 1);
        rs0 += __shfl_xor_sync(0xffffffffu, rs0, 2);
        rs1 += __shfl_xor_sync(0xffffffffu, rs1, 1);
        rs1 += __shfl_xor_sync(0xffffffffu, rs1, 2);
        l0 = l0 * a0 + rs0;
        l1 = l1 * a1 + rs1;
        m0 = mx0; m1 = mx1;
#pragma unroll
        for (int n = 0; n < 8; ++n) {
            o[n][0] *= a0; o[n][1] *= a0; o[n][2] *= a1; o[n][3] *= a1;
        }

        // P -> fp16 smem (warp-private rows)
#pragma unroll
        for (int n = 0; n < 8; ++n) {
            *reinterpret_cast<uint32_t*>(&Ph[ar * ATS + n * 8 + 2 * ac]) =
                pack_h2(s[n][0], s[n][1]);
            *reinterpret_cast<uint32_t*>(&Ph[(ar + 8) * ATS + n * 8 + 2 * ac]) =
                pack_h2(s[n][2], s[n][3]);
        }
        __syncwarp();

        // O += P @ V (V B-frags via ldmatrix.trans on row-major Vh)
#pragma unroll
        for (int ks = 0; ks < 4; ++ks) {
            uint32_t afr[4];
            uint32_t ad = pb + ((warp * 16 + arow) * ATS + ks * 16 + acol) * 2;
            ldsm_x4(afr, ad);
#pragma unroll
            for (int np = 0; np < 4; ++np) {
                uint32_t bfr[4];
                uint32_t vd = vb + ((ks * 16 + trow) * ATS + np * 16 + tcol) * 2;
                ldsm_x4_t(bfr, vd);
                mma_f16(o[2 * np],     afr, bfr[0], bfr[1]);
                mma_f16(o[2 * np + 1], afr, bfr[2], bfr[3]);
            }
        }
    }

    // Epilogue: unnormalized partial O + (m, l)
    float* op = g_Opart + ((size_t)split * NROWS_C + (size_t)b * S_C + q0) * DK_C;
    const int cb = ac * 2;
#pragma unroll
    for (int n = 0; n < 8; ++n) {
        int col = n * 8 + cb;
        *reinterpret_cast<float2*>(&op[(size_t)ar * DK_C + col]) =
            make_float2(o[n][0], o[n][1]);
        *reinterpret_cast<float2*>(&op[(size_t)(ar + 8) * DK_C + col]) =
            make_float2(o[n][2], o[n][3]);
    }
    if (ac == 0) {
        size_t base = (size_t)split * NROWS_C + (size_t)b * S_C + q0;
        g_m[base + ar] = m0;     g_l[base + ar] = l0;
        g_m[base + ar + 8] = m1; g_l[base + ar + 8] = l1;
    }
}

// ---------------------------------------------------------------------------
// Kernel 3: combine partials across splits.
// ---------------------------------------------------------------------------
__global__ __launch_bounds__(256)
void combine_kernel(float* __restrict__ out)
{
    int idx = blockIdx.x * 256 + threadIdx.x;
    int row = idx >> 4;
    int c4  = (idx & 15) * 4;

    float ms[NSPLIT];
    float m = -1e30f;
#pragma unroll
    for (int s = 0; s < NSPLIT; ++s) {
        ms[s] = g_m[(size_t)s * NROWS_C + row];
        m = fmaxf(m, ms[s]);
    }
    float l = 0.f;
    float ox = 0.f, oy = 0.f, oz = 0.f, ow = 0.f;
#pragma unroll
    for (int s = 0; s < NSPLIT; ++s) {
        float w = exp2_approx(ms[s] - m);
        l += g_l[(size_t)s * NROWS_C + row] * w;
        float4 p = *reinterpret_cast<const float4*>(
            &g_Opart[((size_t)s * NROWS_C + row) * DK_C + c4]);
        ox += p.x * w; oy += p.y * w; oz += p.z * w; ow += p.w * w;
    }
    float inv = 1.f / l;
    *reinterpret_cast<float4*>(&out[(size_t)row * DK_C + c4]) =
        make_float4(ox * inv, oy * inv, oz * inv, ow * inv);
}

// ---------------------------------------------------------------------------
extern "C" void kernel_launch(void* const* d_in, const int* in_sizes, int n_in,
                              void* d_out, int out_size) {
    (void)in_sizes; (void)n_in; (void)out_size;
    const float* emb = (const float*)d_in[0];
    const float* Wq  = (const float*)d_in[1];
    const float* bq  = (const float*)d_in[2];
    const float* Wk  = (const float*)d_in[3];
    const float* bk  = (const float*)d_in[4];
    const float* Wv  = (const float*)d_in[5];
    const float* bv  = (const float*)d_in[6];

    wconv_kernel<<<(192 * 1024) / 256, 256>>>(Wq, Wk, Wv);
    dim3 qgrid(NROWS_C / 128, 3);
    qkv_h_kernel<<<qgrid, 256>>>(emb, bq, bk, bv);
    dim3 agrid(S_C / 64, B_C, NSPLIT);
    attn_kernel<<<agrid, 128>>>();
    combine_kernel<<<(NROWS_C * 16) / 256, 256>>>((float*)d_out);
}

// round 9
// speedup vs baseline: 1.6499x; 1.6499x over previous
#include <cuda_runtime.h>
#include <cuda_fp16.h>
#include <cstdint>

#define D_MODEL_C 1024
#define DK_C 64
#define B_C 4
#define S_C 4096
#define NROWS_C (B_C * S_C)
#define NSPLIT 4
#define KV_PER_SPLIT (S_C / NSPLIT)          // 1024
#define TILES_PER_SPLIT (KV_PER_SPLIT / 64)  // 16
#define QSC 0.1803368801111204f              // log2(e)/sqrt(64)

// Scratch. Static device arrays: allocation-free.
__device__ __half g_Qh[NROWS_C * DK_C];      // pre-scaled by QSC
__device__ __half g_Kh[NROWS_C * DK_C];
__device__ __half g_Vh[NROWS_C * DK_C];
__device__ float g_Opart[NSPLIT * NROWS_C * DK_C];
__device__ float g_m[NSPLIT * NROWS_C];
__device__ float g_l[NSPLIT * NROWS_C];

static __device__ __forceinline__ uint32_t smem_to_u32(const void* p) {
    uint32_t a;
    asm("{ .reg .u64 t; cvta.to.shared.u64 t, %1; cvt.u32.u64 %0, t; }"
        : "=r"(a) : "l"(p));
    return a;
}
static __device__ __forceinline__ float exp2_approx(float x) {
    float y;
    asm("ex2.approx.f32 %0, %1;" : "=f"(y) : "f"(x));
    return y;
}
static __device__ __forceinline__ uint32_t f2tf32(float f) {
    uint32_t u;
    asm("cvt.rna.tf32.f32 %0, %1;" : "=r"(u) : "f"(f));
    return u;
}
static __device__ __forceinline__ float tf32r(float f) {
    return __uint_as_float(f2tf32(f));
}
static __device__ __forceinline__ void mma_tf32(float c[4], const uint32_t a[4], const uint32_t b[2]) {
    asm volatile(
        "mma.sync.aligned.m16n8k8.row.col.f32.tf32.tf32.f32 "
        "{%0,%1,%2,%3}, {%4,%5,%6,%7}, {%8,%9}, {%0,%1,%2,%3};\n"
        : "+f"(c[0]), "+f"(c[1]), "+f"(c[2]), "+f"(c[3])
        : "r"(a[0]), "r"(a[1]), "r"(a[2]), "r"(a[3]), "r"(b[0]), "r"(b[1]));
}
static __device__ __forceinline__ void ldsm_x4(uint32_t a[4], uint32_t addr) {
    asm volatile("ldmatrix.sync.aligned.m8n8.x4.shared.b16 {%0,%1,%2,%3}, [%4];"
        : "=r"(a[0]), "=r"(a[1]), "=r"(a[2]), "=r"(a[3]) : "r"(addr));
}
static __device__ __forceinline__ void ldsm_x4_t(uint32_t a[4], uint32_t addr) {
    asm volatile("ldmatrix.sync.aligned.m8n8.x4.trans.shared.b16 {%0,%1,%2,%3}, [%4];"
        : "=r"(a[0]), "=r"(a[1]), "=r"(a[2]), "=r"(a[3]) : "r"(addr));
}
static __device__ __forceinline__ void mma_f16(float c[4], const uint32_t a[4],
                                               uint32_t b0, uint32_t b1) {
    asm volatile(
        "mma.sync.aligned.m16n8k16.row.col.f32.f16.f16.f32 "
        "{%0,%1,%2,%3}, {%4,%5,%6,%7}, {%8,%9}, {%0,%1,%2,%3};"
        : "+f"(c[0]), "+f"(c[1]), "+f"(c[2]), "+f"(c[3])
        : "r"(a[0]), "r"(a[1]), "r"(a[2]), "r"(a[3]), "r"(b0), "r"(b1));
}
static __device__ __forceinline__ uint32_t pack_h2(float x, float y) {
    __half2 h = __floats2half2_rn(x, y);
    return *reinterpret_cast<uint32_t*>(&h);
}

// ---------------------------------------------------------------------------
// Kernel 1: QKV projection, single-pass TF32 (round-6 structure, measured
// 63.7us), epilogue emits fp16 (Q pre-scaled by QSC).
// Grid (NROWS/128, 3). Block 256 (8 warps). CTA tile 128x64.
// ---------------------------------------------------------------------------
#define QKC 32
#define QES_S 36    // 36 mod 32 = 4 -> a-frag banks 4g+ac distinct
#define QWS_S 72    // 72 mod 32 = 8 -> b-frag banks 8ac+g distinct

__global__ __launch_bounds__(256)
void qkv_proj_kernel(const float* __restrict__ emb,
                     const float* __restrict__ Wq, const float* __restrict__ bq,
                     const float* __restrict__ Wk, const float* __restrict__ bk,
                     const float* __restrict__ Wv, const float* __restrict__ bv)
{
    __shared__ float Es[128 * QES_S];
    __shared__ float Ws[QKC * QWS_S];

    const int tid  = threadIdx.x;
    const int warp = tid >> 5;
    const int lane = tid & 31;
    const int rs   = warp & 3;
    const int ch   = warp >> 2;
    const int row0 = blockIdx.x * 128;
    const int mat  = blockIdx.y;

    const float* W    = (mat == 0) ? Wq : (mat == 1) ? Wk : Wv;
    const float* bias = (mat == 0) ? bq : (mat == 1) ? bk : bv;
    __half* outp      = (mat == 0) ? g_Qh : (mat == 1) ? g_Kh : g_Vh;
    const float osc   = (mat == 0) ? QSC : 1.0f;

    float acc[2][4][4];
#pragma unroll
    for (int mt = 0; mt < 2; ++mt)
#pragma unroll
        for (int n = 0; n < 4; ++n)
#pragma unroll
            for (int j = 0; j < 4; ++j) acc[mt][n][j] = 0.f;

    const int g  = lane >> 2;
    const int ac = lane & 3;

    const int er  = tid >> 3;
    const int ec4 = (tid & 7) * 4;
    const int wr  = tid >> 4;
    const int wc4 = (tid & 15) * 4;

    for (int kc = 0; kc < D_MODEL_C / QKC; ++kc) {
        __syncthreads();
#pragma unroll
        for (int i = 0; i < 4; ++i) {
            int r = er + i * 32;
            float4 v = *reinterpret_cast<const float4*>(
                &emb[(size_t)(row0 + r) * D_MODEL_C + kc * QKC + ec4]);
            *reinterpret_cast<float4*>(&Es[r * QES_S + ec4]) =
                make_float4(tf32r(v.x), tf32r(v.y), tf32r(v.z), tf32r(v.w));
        }
#pragma unroll
        for (int i = 0; i < 2; ++i) {
            int r = wr + i * 16;
            float4 v = *reinterpret_cast<const float4*>(
                &W[(size_t)(kc * QKC + r) * DK_C + wc4]);
            *reinterpret_cast<float4*>(&Ws[r * QWS_S + wc4]) =
                make_float4(tf32r(v.x), tf32r(v.y), tf32r(v.z), tf32r(v.w));
        }
        __syncthreads();
#pragma unroll
        for (int ks = 0; ks < QKC / 8; ++ks) {
            uint32_t a[2][4];
#pragma unroll
            for (int mt = 0; mt < 2; ++mt) {
                const int r0 = rs * 32 + mt * 16 + g;
                a[mt][0] = __float_as_uint(Es[r0 * QES_S + ks * 8 + ac]);
                a[mt][1] = __float_as_uint(Es[(r0 + 8) * QES_S + ks * 8 + ac]);
                a[mt][2] = __float_as_uint(Es[r0 * QES_S + ks * 8 + ac + 4]);
                a[mt][3] = __float_as_uint(Es[(r0 + 8) * QES_S + ks * 8 + ac + 4]);
            }
            const int brow = ks * 8 + ac;
#pragma unroll
            for (int n = 0; n < 4; ++n) {
                const int bcol = ch * 32 + n * 8 + g;
                uint32_t b[2];
                b[0] = __float_as_uint(Ws[brow * QWS_S + bcol]);
                b[1] = __float_as_uint(Ws[(brow + 4) * QWS_S + bcol]);
                mma_tf32(acc[0][n], a[0], b);
                mma_tf32(acc[1][n], a[1], b);
            }
        }
    }
    // Epilogue: bias add, scale (Q only), fp16 stores
    const int cb = ac * 2;
#pragma unroll
    for (int mt = 0; mt < 2; ++mt) {
        const int r = row0 + rs * 32 + mt * 16 + g;
#pragma unroll
        for (int n = 0; n < 4; ++n) {
            int col = ch * 32 + n * 8 + cb;
            float b0 = bias[col], b1 = bias[col + 1];
            *reinterpret_cast<__half2*>(&outp[(size_t)r * DK_C + col]) =
                __floats2half2_rn((acc[mt][n][0] + b0) * osc, (acc[mt][n][1] + b1) * osc);
            *reinterpret_cast<__half2*>(&outp[(size_t)(r + 8) * DK_C + col]) =
                __floats2half2_rn((acc[mt][n][2] + b0) * osc, (acc[mt][n][3] + b1) * osc);
        }
    }
}

// ---------------------------------------------------------------------------
// Kernel 2: flash attention, fp16 m16n8k16 + ldmatrix, split-KV (4).
// Br=Bc=64, 4 warps. Loader = pure 16B copies (inputs already fp16).
// Q staged in Ph region (reused after fragment extraction).
// ---------------------------------------------------------------------------
#define ATS 72    // halves; 144B row stride -> LDSM rows at 16B*i mod 128, distinct

__global__ __launch_bounds__(128)
void attn_kernel()
{
    __shared__ __align__(16) __half Kh[64 * ATS];
    __shared__ __align__(16) __half Vh[64 * ATS];
    __shared__ __align__(16) __half Ph[64 * ATS];   // Q staging, then P

    const int tid   = threadIdx.x;
    const int warp  = tid >> 5;
    const int lane  = tid & 31;
    const int b     = blockIdx.y;
    const int q0    = blockIdx.x * 64;
    const int split = blockIdx.z;
    const int t0t   = split * TILES_PER_SPLIT;

    const __half* Qg = g_Qh + ((size_t)b * S_C + q0) * DK_C;
    const __half* Kg = g_Kh + (size_t)b * S_C * DK_C;
    const __half* Vg = g_Vh + (size_t)b * S_C * DK_C;

    const uint32_t kb = smem_to_u32(Kh);
    const uint32_t vb = smem_to_u32(Vh);
    const uint32_t pb = smem_to_u32(Ph);
    const int l8 = lane & 7;
    const int arow = l8 + ((lane >> 3) & 1) * 8;       // A pattern
    const int acol = ((lane >> 4) & 1) * 8;
    const int brow = l8 + ((lane >> 4) & 1) * 8;       // B (K-major) pattern
    const int bcol = ((lane >> 3) & 1) * 8;
    const int trow = l8 + ((lane >> 3) & 1) * 8;       // B-trans (V) pattern
    const int tcol = ((lane >> 4) & 1) * 8;

    // Stage Q (fp16, pre-scaled) into Ph, extract fragments
#pragma unroll
    for (int i = 0; i < 4; ++i) {
        int idx = tid + i * 128;
        int r = idx >> 3, grp = idx & 7;
        *reinterpret_cast<uint4*>(&Ph[r * ATS + grp * 8]) =
            reinterpret_cast<const uint4*>(Qg + (size_t)r * DK_C)[grp];
    }
    __syncthreads();
    uint32_t qf[4][4];
#pragma unroll
    for (int ks = 0; ks < 4; ++ks)
        ldsm_x4(qf[ks], pb + ((warp * 16 + arow) * ATS + ks * 16 + acol) * 2);

    float o[8][4];
#pragma unroll
    for (int n = 0; n < 8; ++n)
#pragma unroll
        for (int j = 0; j < 4; ++j) o[n][j] = 0.f;
    float m0 = -1e30f, m1 = -1e30f, l0 = 0.f, l1 = 0.f;

    const int g  = lane >> 2;
    const int ac = lane & 3;
    const int ar = warp * 16 + g;

    for (int tt = 0; tt < TILES_PER_SPLIT; ++tt) {
        const int t = t0t + tt;
        __syncthreads();   // all warps done with Kh/Vh/Ph (incl. Q frags iter 0)
        const __half* Kt = Kg + (size_t)t * 64 * DK_C;
        const __half* Vt = Vg + (size_t)t * 64 * DK_C;
#pragma unroll
        for (int i = 0; i < 4; ++i) {
            int idx = tid + i * 128;
            int r = idx >> 3, grp = idx & 7;
            *reinterpret_cast<uint4*>(&Kh[r * ATS + grp * 8]) =
                reinterpret_cast<const uint4*>(Kt + (size_t)r * DK_C)[grp];
            *reinterpret_cast<uint4*>(&Vh[r * ATS + grp * 8]) =
                reinterpret_cast<const uint4*>(Vt + (size_t)r * DK_C)[grp];
        }
        __syncthreads();

        // S = Qs @ K^T (log2-domain logits; scale folded into Q)
        float s[8][4];
#pragma unroll
        for (int n = 0; n < 8; ++n)
#pragma unroll
            for (int j = 0; j < 4; ++j) s[n][j] = 0.f;
#pragma unroll
        for (int ks = 0; ks < 4; ++ks) {
#pragma unroll
            for (int np = 0; np < 4; ++np) {
                uint32_t bfr[4];
                ldsm_x4(bfr, kb + ((np * 16 + brow) * ATS + ks * 16 + bcol) * 2);
                mma_f16(s[2 * np],     qf[ks], bfr[0], bfr[1]);
                mma_f16(s[2 * np + 1], qf[ks], bfr[2], bfr[3]);
            }
        }

        // Online softmax
        float mx0 = m0, mx1 = m1;
#pragma unroll
        for (int n = 0; n < 8; ++n) {
            mx0 = fmaxf(mx0, fmaxf(s[n][0], s[n][1]));
            mx1 = fmaxf(mx1, fmaxf(s[n][2], s[n][3]));
        }
        mx0 = fmaxf(mx0, __shfl_xor_sync(0xffffffffu, mx0, 1));
        mx0 = fmaxf(mx0, __shfl_xor_sync(0xffffffffu, mx0, 2));
        mx1 = fmaxf(mx1, __shfl_xor_sync(0xffffffffu, mx1, 1));
        mx1 = fmaxf(mx1, __shfl_xor_sync(0xffffffffu, mx1, 2));
        float a0 = exp2_approx(m0 - mx0);
        float a1 = exp2_approx(m1 - mx1);
        float rs0 = 0.f, rs1 = 0.f;
#pragma unroll
        for (int n = 0; n < 8; ++n) {
            s[n][0] = exp2_approx(s[n][0] - mx0);
            s[n][1] = exp2_approx(s[n][1] - mx0);
            s[n][2] = exp2_approx(s[n][2] - mx1);
            s[n][3] = exp2_approx(s[n][3] - mx1);
            rs0 += s[n][0] + s[n][1];
            rs1 += s[n][2] + s[n][3];
        }
        rs0 += __shfl_xor_sync(0xffffffffu, rs0, 1);
        rs0 += __shfl_xor_sync(0xffffffffu, rs0, 2);
        rs1 += __shfl_xor_sync(0xffffffffu, rs1, 1);
        rs1 += __shfl_xor_sync(0xffffffffu, rs1, 2);
        l0 = l0 * a0 + rs0;
        l1 = l1 * a1 + rs1;
        m0 = mx0; m1 = mx1;
#pragma unroll
        for (int n = 0; n < 8; ++n) {
            o[n][0] *= a0; o[n][1] *= a0; o[n][2] *= a1; o[n][3] *= a1;
        }

        // P -> fp16 smem (warp-private rows)
#pragma unroll
        for (int n = 0; n < 8; ++n) {
            *reinterpret_cast<uint32_t*>(&Ph[ar * ATS + n * 8 + 2 * ac]) =
                pack_h2(s[n][0], s[n][1]);
            *reinterpret_cast<uint32_t*>(&Ph[(ar + 8) * ATS + n * 8 + 2 * ac]) =
                pack_h2(s[n][2], s[n][3]);
        }
        __syncwarp();

        // O += P @ V (V B-frags via ldmatrix.trans on row-major Vh)
#pragma unroll
        for (int ks = 0; ks < 4; ++ks) {
            uint32_t afr[4];
            ldsm_x4(afr, pb + ((warp * 16 + arow) * ATS + ks * 16 + acol) * 2);
#pragma unroll
            for (int np = 0; np < 4; ++np) {
                uint32_t bfr[4];
                ldsm_x4_t(bfr, vb + ((ks * 16 + trow) * ATS + np * 16 + tcol) * 2);
                mma_f16(o[2 * np],     afr, bfr[0], bfr[1]);
                mma_f16(o[2 * np + 1], afr, bfr[2], bfr[3]);
            }
        }
    }

    // Epilogue: unnormalized partial O + (m, l)
    float* op = g_Opart + ((size_t)split * NROWS_C + (size_t)b * S_C + q0) * DK_C;
    const int cb = ac * 2;
#pragma unroll
    for (int n = 0; n < 8; ++n) {
        int col = n * 8 + cb;
        *reinterpret_cast<float2*>(&op[(size_t)ar * DK_C + col]) =
            make_float2(o[n][0], o[n][1]);
        *reinterpret_cast<float2*>(&op[(size_t)(ar + 8) * DK_C + col]) =
            make_float2(o[n][2], o[n][3]);
    }
    if (ac == 0) {
        size_t base = (size_t)split * NROWS_C + (size_t)b * S_C + q0;
        g_m[base + ar] = m0;     g_l[base + ar] = l0;
        g_m[base + ar + 8] = m1; g_l[base + ar + 8] = l1;
    }
}

// ---------------------------------------------------------------------------
// Kernel 3: combine partials across splits.
// ---------------------------------------------------------------------------
__global__ __launch_bounds__(256)
void combine_kernel(float* __restrict__ out)
{
    int idx = blockIdx.x * 256 + threadIdx.x;
    int row = idx >> 4;
    int c4  = (idx & 15) * 4;

    float ms[NSPLIT];
    float m = -1e30f;
#pragma unroll
    for (int s = 0; s < NSPLIT; ++s) {
        ms[s] = g_m[(size_t)s * NROWS_C + row];
        m = fmaxf(m, ms[s]);
    }
    float l = 0.f;
    float ox = 0.f, oy = 0.f, oz = 0.f, ow = 0.f;
#pragma unroll
    for (int s = 0; s < NSPLIT; ++s) {
        float w = exp2_approx(ms[s] - m);
        l += g_l[(size_t)s * NROWS_C + row] * w;
        float4 p = *reinterpret_cast<const float4*>(
            &g_Opart[((size_t)s * NROWS_C + row) * DK_C + c4]);
        ox += p.x * w; oy += p.y * w; oz += p.z * w; ow += p.w * w;
    }
    float inv = 1.f / l;
    *reinterpret_cast<float4*>(&out[(size_t)row * DK_C + c4]) =
        make_float4(ox * inv, oy * inv, oz * inv, ow * inv);
}

// ---------------------------------------------------------------------------
extern "C" void kernel_launch(void* const* d_in, const int* in_sizes, int n_in,
                              void* d_out, int out_size) {
    (void)in_sizes; (void)n_in; (void)out_size;
    const float* emb = (const float*)d_in[0];
    const float* Wq  = (const float*)d_in[1];
    const float* bq  = (const float*)d_in[2];
    const float* Wk  = (const float*)d_in[3];
    const float* bk  = (const float*)d_in[4];
    const float* Wv  = (const float*)d_in[5];
    const float* bv  = (const float*)d_in[6];

    dim3 qgrid(NROWS_C / 128, 3);
    qkv_proj_kernel<<<qgrid, 256>>>(emb, Wq, bq, Wk, bk, Wv, bv);
    dim3 agrid(S_C / 64, B_C, NSPLIT);
    attn_kernel<<<agrid, 128>>>();
    combine_kernel<<<(NROWS_C * 16) / 256, 256>>>((float*)d_out);
}

// round 11
// speedup vs baseline: 1.8123x; 1.0984x over previous
#include <cuda_runtime.h>
#include <cuda_fp16.h>
#include <cstdint>

#define D_MODEL_C 1024
#define DK_C 64
#define B_C 4
#define S_C 4096
#define NROWS_C (B_C * S_C)
#define NSPLIT 4
#define KV_PER_SPLIT (S_C / NSPLIT)          // 1024
#define TILES_PER_SPLIT (KV_PER_SPLIT / 64)  // 16
#define QSC 0.1803368801111204f              // log2(e)/sqrt(64)

// Scratch. Static device arrays: allocation-free.
__device__ __half g_Qh[NROWS_C * DK_C];      // pre-scaled by QSC
__device__ __half g_Kh[NROWS_C * DK_C];
__device__ __half g_Vh[NROWS_C * DK_C];
__device__ float g_Opart[NSPLIT * NROWS_C * DK_C];
__device__ float g_m[NSPLIT * NROWS_C];
__device__ float g_l[NSPLIT * NROWS_C];

static __device__ __forceinline__ uint32_t smem_to_u32(const void* p) {
    uint32_t a;
    asm("{ .reg .u64 t; cvta.to.shared.u64 t, %1; cvt.u32.u64 %0, t; }"
        : "=r"(a) : "l"(p));
    return a;
}
static __device__ __forceinline__ float exp2_approx(float x) {
    float y;
    asm("ex2.approx.f32 %0, %1;" : "=f"(y) : "f"(x));
    return y;
}
static __device__ __forceinline__ void ldsm_x4(uint32_t a[4], uint32_t addr) {
    asm volatile("ldmatrix.sync.aligned.m8n8.x4.shared.b16 {%0,%1,%2,%3}, [%4];"
        : "=r"(a[0]), "=r"(a[1]), "=r"(a[2]), "=r"(a[3]) : "r"(addr));
}
static __device__ __forceinline__ void ldsm_x4_t(uint32_t a[4], uint32_t addr) {
    asm volatile("ldmatrix.sync.aligned.m8n8.x4.trans.shared.b16 {%0,%1,%2,%3}, [%4];"
        : "=r"(a[0]), "=r"(a[1]), "=r"(a[2]), "=r"(a[3]) : "r"(addr));
}
static __device__ __forceinline__ void mma_f16(float c[4], const uint32_t a[4],
                                               uint32_t b0, uint32_t b1) {
    asm volatile(
        "mma.sync.aligned.m16n8k16.row.col.f32.f16.f16.f32 "
        "{%0,%1,%2,%3}, {%4,%5,%6,%7}, {%8,%9}, {%0,%1,%2,%3};"
        : "+f"(c[0]), "+f"(c[1]), "+f"(c[2]), "+f"(c[3])
        : "r"(a[0]), "r"(a[1]), "r"(a[2]), "r"(a[3]), "r"(b0), "r"(b1));
}
static __device__ __forceinline__ uint32_t pack_h2(float x, float y) {
    __half2 h = __floats2half2_rn(x, y);
    return *reinterpret_cast<uint32_t*>(&h);
}
static __device__ __forceinline__ uint4 cvt8_h(float4 v0, float4 v1) {
    return make_uint4(pack_h2(v0.x, v0.y), pack_h2(v0.z, v0.w),
                      pack_h2(v1.x, v1.y), pack_h2(v1.z, v1.w));
}

// ---------------------------------------------------------------------------
// Kernel 1: QKV projection, fp16 m16n8k16 + ldmatrix.
// Grid (NROWS/128, 3). Block 256 (8 warps). CTA tile 128x64, K-chunk 64.
// W tile kept [k][n]; B-fragments via ldmatrix.trans (no pre-transpose).
// Epilogue emits fp16 (Q pre-scaled by QSC).
// ---------------------------------------------------------------------------
#define QKC 64
#define EH 72    // halves stride (144B): ldsm row addrs 16B*i mod 128 distinct
#define WH 72

__global__ __launch_bounds__(256)
void qkv_proj_kernel(const float* __restrict__ emb,
                     const float* __restrict__ Wq, const float* __restrict__ bq,
                     const float* __restrict__ Wk, const float* __restrict__ bk,
                     const float* __restrict__ Wv, const float* __restrict__ bv)
{
    __shared__ __align__(16) __half Es[128 * EH];   // emb tile 128x64
    __shared__ __align__(16) __half Ws[64 * WH];    // W tile [k 0..63][n 0..63]

    const int tid  = threadIdx.x;
    const int warp = tid >> 5;
    const int lane = tid & 31;
    const int rs   = warp & 3;      // row slab (32 rows)
    const int ch   = warp >> 2;     // col half (32 cols)
    const int row0 = blockIdx.x * 128;
    const int mat  = blockIdx.y;

    const float* W    = (mat == 0) ? Wq : (mat == 1) ? Wk : Wv;
    const float* bias = (mat == 0) ? bq : (mat == 1) ? bk : bv;
    __half* outp      = (mat == 0) ? g_Qh : (mat == 1) ? g_Kh : g_Vh;
    const float osc   = (mat == 0) ? QSC : 1.0f;

    float acc[2][4][4];
#pragma unroll
    for (int mt = 0; mt < 2; ++mt)
#pragma unroll
        for (int n = 0; n < 4; ++n)
#pragma unroll
            for (int j = 0; j < 4; ++j) acc[mt][n][j] = 0.f;

    const uint32_t esb = smem_to_u32(Es);
    const uint32_t wsb = smem_to_u32(Ws);
    const int l8 = lane & 7;
    const int arow = l8 + ((lane >> 3) & 1) * 8;   // A-frag x4 pattern
    const int acol = ((lane >> 4) & 1) * 8;
    const int trow = l8 + ((lane >> 3) & 1) * 8;   // B-trans x4 pattern
    const int tcol = ((lane >> 4) & 1) * 8;

    for (int kc = 0; kc < D_MODEL_C / QKC; ++kc) {
        __syncthreads();
        // emb tile 128x64: 1024 groups of 8 halves, 4 per thread
#pragma unroll
        for (int i = 0; i < 4; ++i) {
            int idx = tid + i * 256;
            int r = idx >> 3, grp = idx & 7;
            const float* src = emb + (size_t)(row0 + r) * D_MODEL_C + kc * QKC + grp * 8;
            float4 v0 = *reinterpret_cast<const float4*>(src);
            float4 v1 = *reinterpret_cast<const float4*>(src + 4);
            *reinterpret_cast<uint4*>(&Es[r * EH + grp * 8]) = cvt8_h(v0, v1);
        }
        // W tile 64x64 [k][n]: 512 groups, 2 per thread
#pragma unroll
        for (int i = 0; i < 2; ++i) {
            int idx = tid + i * 256;
            int r = idx >> 3, grp = idx & 7;
            const float* src = W + (size_t)(kc * QKC + r) * DK_C + grp * 8;
            float4 v0 = *reinterpret_cast<const float4*>(src);
            float4 v1 = *reinterpret_cast<const float4*>(src + 4);
            *reinterpret_cast<uint4*>(&Ws[r * WH + grp * 8]) = cvt8_h(v0, v1);
        }
        __syncthreads();
#pragma unroll
        for (int ks = 0; ks < QKC / 16; ++ks) {
            uint32_t a[2][4];
#pragma unroll
            for (int mt = 0; mt < 2; ++mt)
                ldsm_x4(a[mt], esb + ((rs * 32 + mt * 16 + arow) * EH + ks * 16 + acol) * 2);
#pragma unroll
            for (int np = 0; np < 2; ++np) {
                uint32_t b[4];
                ldsm_x4_t(b, wsb + ((ks * 16 + trow) * WH + ch * 32 + np * 16 + tcol) * 2);
                mma_f16(acc[0][2 * np],     a[0], b[0], b[1]);
                mma_f16(acc[1][2 * np],     a[1], b[0], b[1]);
                mma_f16(acc[0][2 * np + 1], a[0], b[2], b[3]);
                mma_f16(acc[1][2 * np + 1], a[1], b[2], b[3]);
            }
        }
    }
    // Epilogue: bias add, scale (Q only), fp16 stores
    const int g  = lane >> 2;
    const int cb = (lane & 3) * 2;
#pragma unroll
    for (int mt = 0; mt < 2; ++mt) {
        const int r = row0 + rs * 32 + mt * 16 + g;
#pragma unroll
        for (int n = 0; n < 4; ++n) {
            int col = ch * 32 + n * 8 + cb;
            float b0 = bias[col], b1 = bias[col + 1];
            *reinterpret_cast<__half2*>(&outp[(size_t)r * DK_C + col]) =
                __floats2half2_rn((acc[mt][n][0] + b0) * osc, (acc[mt][n][1] + b1) * osc);
            *reinterpret_cast<__half2*>(&outp[(size_t)(r + 8) * DK_C + col]) =
                __floats2half2_rn((acc[mt][n][2] + b0) * osc, (acc[mt][n][3] + b1) * osc);
        }
    }
}

// ---------------------------------------------------------------------------
// Kernel 2: flash attention, fp16 m16n8k16 + ldmatrix, split-KV (4).
// (frozen from round 9 — measured ~78us)
// ---------------------------------------------------------------------------
#define ATS 72

__global__ __launch_bounds__(128)
void attn_kernel()
{
    __shared__ __align__(16) __half Kh[64 * ATS];
    __shared__ __align__(16) __half Vh[64 * ATS];
    __shared__ __align__(16) __half Ph[64 * ATS];   // Q staging, then P

    const int tid   = threadIdx.x;
    const int warp  = tid >> 5;
    const int lane  = tid & 31;
    const int b     = blockIdx.y;
    const int q0    = blockIdx.x * 64;
    const int split = blockIdx.z;
    const int t0t   = split * TILES_PER_SPLIT;

    const __half* Qg = g_Qh + ((size_t)b * S_C + q0) * DK_C;
    const __half* Kg = g_Kh + (size_t)b * S_C * DK_C;
    const __half* Vg = g_Vh + (size_t)b * S_C * DK_C;

    const uint32_t kb = smem_to_u32(Kh);
    const uint32_t vb = smem_to_u32(Vh);
    const uint32_t pb = smem_to_u32(Ph);
    const int l8 = lane & 7;
    const int arow = l8 + ((lane >> 3) & 1) * 8;
    const int acol = ((lane >> 4) & 1) * 8;
    const int brow = l8 + ((lane >> 4) & 1) * 8;
    const int bcol = ((lane >> 3) & 1) * 8;
    const int trow = l8 + ((lane >> 3) & 1) * 8;
    const int tcol = ((lane >> 4) & 1) * 8;

#pragma unroll
    for (int i = 0; i < 4; ++i) {
        int idx = tid + i * 128;
        int r = idx >> 3, grp = idx & 7;
        *reinterpret_cast<uint4*>(&Ph[r * ATS + grp * 8]) =
            reinterpret_cast<const uint4*>(Qg + (size_t)r * DK_C)[grp];
    }
    __syncthreads();
    uint32_t qf[4][4];
#pragma unroll
    for (int ks = 0; ks < 4; ++ks)
        ldsm_x4(qf[ks], pb + ((warp * 16 + arow) * ATS + ks * 16 + acol) * 2);

    float o[8][4];
#pragma unroll
    for (int n = 0; n < 8; ++n)
#pragma unroll
        for (int j = 0; j < 4; ++j) o[n][j] = 0.f;
    float m0 = -1e30f, m1 = -1e30f, l0 = 0.f, l1 = 0.f;

    const int g  = lane >> 2;
    const int ac = lane & 3;
    const int ar = warp * 16 + g;

    for (int tt = 0; tt < TILES_PER_SPLIT; ++tt) {
        const int t = t0t + tt;
        __syncthreads();
        const __half* Kt = Kg + (size_t)t * 64 * DK_C;
        const __half* Vt = Vg + (size_t)t * 64 * DK_C;
#pragma unroll
        for (int i = 0; i < 4; ++i) {
            int idx = tid + i * 128;
            int r = idx >> 3, grp = idx & 7;
            *reinterpret_cast<uint4*>(&Kh[r * ATS + grp * 8]) =
                reinterpret_cast<const uint4*>(Kt + (size_t)r * DK_C)[grp];
            *reinterpret_cast<uint4*>(&Vh[r * ATS + grp * 8]) =
                reinterpret_cast<const uint4*>(Vt + (size_t)r * DK_C)[grp];
        }
        __syncthreads();

        float s[8][4];
#pragma unroll
        for (int n = 0; n < 8; ++n)
#pragma unroll
            for (int j = 0; j < 4; ++j) s[n][j] = 0.f;
#pragma unroll
        for (int ks = 0; ks < 4; ++ks) {
#pragma unroll
            for (int np = 0; np < 4; ++np) {
                uint32_t bfr[4];
                ldsm_x4(bfr, kb + ((np * 16 + brow) * ATS + ks * 16 + bcol) * 2);
                mma_f16(s[2 * np],     qf[ks], bfr[0], bfr[1]);
                mma_f16(s[2 * np + 1], qf[ks], bfr[2], bfr[3]);
            }
        }

        float mx0 = m0, mx1 = m1;
#pragma unroll
        for (int n = 0; n < 8; ++n) {
            mx0 = fmaxf(mx0, fmaxf(s[n][0], s[n][1]));
            mx1 = fmaxf(mx1, fmaxf(s[n][2], s[n][3]));
        }
        mx0 = fmaxf(mx0, __shfl_xor_sync(0xffffffffu, mx0, 1));
        mx0 = fmaxf(mx0, __shfl_xor_sync(0xffffffffu, mx0, 2));
        mx1 = fmaxf(mx1, __shfl_xor_sync(0xffffffffu, mx1, 1));
        mx1 = fmaxf(mx1, __shfl_xor_sync(0xffffffffu, mx1, 2));
        float a0 = exp2_approx(m0 - mx0);
        float a1 = exp2_approx(m1 - mx1);
        float rs0 = 0.f, rs1 = 0.f;
#pragma unroll
        for (int n = 0; n < 8; ++n) {
            s[n][0] = exp2_approx(s[n][0] - mx0);
            s[n][1] = exp2_approx(s[n][1] - mx0);
            s[n][2] = exp2_approx(s[n][2] - mx1);
            s[n][3] = exp2_approx(s[n][3] - mx1);
            rs0 += s[n][0] + s[n][1];
            rs1 += s[n][2] + s[n][3];
        }
        rs0 += __shfl_xor_sync(0xffffffffu, rs0, 1);
        rs0 += __shfl_xor_sync(0xffffffffu, rs0, 2);
        rs1 += __shfl_xor_sync(0xffffffffu, rs1, 1);
        rs1 += __shfl_xor_sync(0xffffffffu, rs1, 2);
        l0 = l0 * a0 + rs0;
        l1 = l1 * a1 + rs1;
        m0 = mx0; m1 = mx1;
#pragma unroll
        for (int n = 0; n < 8; ++n) {
            o[n][0] *= a0; o[n][1] *= a0; o[n][2] *= a1; o[n][3] *= a1;
        }

#pragma unroll
        for (int n = 0; n < 8; ++n) {
            *reinterpret_cast<uint32_t*>(&Ph[ar * ATS + n * 8 + 2 * ac]) =
                pack_h2(s[n][0], s[n][1]);
            *reinterpret_cast<uint32_t*>(&Ph[(ar + 8) * ATS + n * 8 + 2 * ac]) =
                pack_h2(s[n][2], s[n][3]);
        }
        __syncwarp();

#pragma unroll
        for (int ks = 0; ks < 4; ++ks) {
            uint32_t afr[4];
            ldsm_x4(afr, pb + ((warp * 16 + arow) * ATS + ks * 16 + acol) * 2);
#pragma unroll
            for (int np = 0; np < 4; ++np) {
                uint32_t bfr[4];
                ldsm_x4_t(bfr, vb + ((ks * 16 + trow) * ATS + np * 16 + tcol) * 2);
                mma_f16(o[2 * np],     afr, bfr[0], bfr[1]);
                mma_f16(o[2 * np + 1], afr, bfr[2], bfr[3]);
            }
        }
    }

    float* op = g_Opart + ((size_t)split * NROWS_C + (size_t)b * S_C + q0) * DK_C;
    const int cb = ac * 2;
#pragma unroll
    for (int n = 0; n < 8; ++n) {
        int col = n * 8 + cb;
        *reinterpret_cast<float2*>(&op[(size_t)ar * DK_C + col]) =
            make_float2(o[n][0], o[n][1]);
        *reinterpret_cast<float2*>(&op[(size_t)(ar + 8) * DK_C + col]) =
            make_float2(o[n][2], o[n][3]);
    }
    if (ac == 0) {
        size_t base = (size_t)split * NROWS_C + (size_t)b * S_C + q0;
        g_m[base + ar] = m0;     g_l[base + ar] = l0;
        g_m[base + ar + 8] = m1; g_l[base + ar + 8] = l1;
    }
}

// ---------------------------------------------------------------------------
// Kernel 3: combine partials across splits.
// ---------------------------------------------------------------------------
__global__ __launch_bounds__(256)
void combine_kernel(float* __restrict__ out)
{
    int idx = blockIdx.x * 256 + threadIdx.x;
    int row = idx >> 4;
    int c4  = (idx & 15) * 4;

    float ms[NSPLIT];
    float m = -1e30f;
#pragma unroll
    for (int s = 0; s < NSPLIT; ++s) {
        ms[s] = g_m[(size_t)s * NROWS_C + row];
        m = fmaxf(m, ms[s]);
    }
    float l = 0.f;
    float ox = 0.f, oy = 0.f, oz = 0.f, ow = 0.f;
#pragma unroll
    for (int s = 0; s < NSPLIT; ++s) {
        float w = exp2_approx(ms[s] - m);
        l += g_l[(size_t)s * NROWS_C + row] * w;
        float4 p = *reinterpret_cast<const float4*>(
            &g_Opart[((size_t)s * NROWS_C + row) * DK_C + c4]);
        ox += p.x * w; oy += p.y * w; oz += p.z * w; ow += p.w * w;
    }
    float inv = 1.f / l;
    *reinterpret_cast<float4*>(&out[(size_t)row * DK_C + c4]) =
        make_float4(ox * inv, oy * inv, oz * inv, ow * inv);
}

// ---------------------------------------------------------------------------
extern "C" void kernel_launch(void* const* d_in, const int* in_sizes, int n_in,
                              void* d_out, int out_size) {
    (void)in_sizes; (void)n_in; (void)out_size;
    const float* emb = (const float*)d_in[0];
    const float* Wq  = (const float*)d_in[1];
    const float* bq  = (const float*)d_in[2];
    const float* Wk  = (const float*)d_in[3];
    const float* bk  = (const float*)d_in[4];
    const float* Wv  = (const float*)d_in[5];
    const float* bv  = (const float*)d_in[6];

    dim3 qgrid(NROWS_C / 128, 3);
    qkv_proj_kernel<<<qgrid, 256>>>(emb, Wq, bq, Wk, bk, Wv, bv);
    dim3 agrid(S_C / 64, B_C, NSPLIT);
    attn_kernel<<<agrid, 128>>>();
    combine_kernel<<<(NROWS_C * 16) / 256, 256>>>((float*)d_out);
}

// round 12
// speedup vs baseline: 2.0817x; 1.1486x over previous
#include <cuda_runtime.h>
#include <cuda_fp16.h>
#include <cstdint>

#define D_MODEL_C 1024
#define DK_C 64
#define B_C 4
#define S_C 4096
#define NROWS_C (B_C * S_C)
#define NSPLIT 4
#define KV_PER_SPLIT (S_C / NSPLIT)          // 1024
#define TILES_PER_SPLIT (KV_PER_SPLIT / 64)  // 16
#define QSC 0.1803368801111204f              // log2(e)/sqrt(64)

// Scratch. Static device arrays: allocation-free.
__device__ __half g_Qh[NROWS_C * DK_C];      // pre-scaled by QSC
__device__ __half g_Kh[NROWS_C * DK_C];
__device__ __half g_Vh[NROWS_C * DK_C];
__device__ float g_Opart[NSPLIT * NROWS_C * DK_C];
__device__ float g_m[NSPLIT * NROWS_C];
__device__ float g_l[NSPLIT * NROWS_C];

static __device__ __forceinline__ uint32_t smem_to_u32(const void* p) {
    uint32_t a;
    asm("{ .reg .u64 t; cvta.to.shared.u64 t, %1; cvt.u32.u64 %0, t; }"
        : "=r"(a) : "l"(p));
    return a;
}
static __device__ __forceinline__ float exp2_approx(float x) {
    float y;
    asm("ex2.approx.f32 %0, %1;" : "=f"(y) : "f"(x));
    return y;
}
static __device__ __forceinline__ void ldsm_x4(uint32_t a[4], uint32_t addr) {
    asm volatile("ldmatrix.sync.aligned.m8n8.x4.shared.b16 {%0,%1,%2,%3}, [%4];"
        : "=r"(a[0]), "=r"(a[1]), "=r"(a[2]), "=r"(a[3]) : "r"(addr));
}
static __device__ __forceinline__ void ldsm_x4_t(uint32_t a[4], uint32_t addr) {
    asm volatile("ldmatrix.sync.aligned.m8n8.x4.trans.shared.b16 {%0,%1,%2,%3}, [%4];"
        : "=r"(a[0]), "=r"(a[1]), "=r"(a[2]), "=r"(a[3]) : "r"(addr));
}
static __device__ __forceinline__ void mma_f16(float c[4], const uint32_t a[4],
                                               uint32_t b0, uint32_t b1) {
    asm volatile(
        "mma.sync.aligned.m16n8k16.row.col.f32.f16.f16.f32 "
        "{%0,%1,%2,%3}, {%4,%5,%6,%7}, {%8,%9}, {%0,%1,%2,%3};"
        : "+f"(c[0]), "+f"(c[1]), "+f"(c[2]), "+f"(c[3])
        : "r"(a[0]), "r"(a[1]), "r"(a[2]), "r"(a[3]), "r"(b0), "r"(b1));
}
static __device__ __forceinline__ uint32_t pack_h2(float x, float y) {
    __half2 h = __floats2half2_rn(x, y);
    return *reinterpret_cast<uint32_t*>(&h);
}
static __device__ __forceinline__ uint4 cvt8_h(float4 v0, float4 v1) {
    return make_uint4(pack_h2(v0.x, v0.y), pack_h2(v0.z, v0.w),
                      pack_h2(v1.x, v1.y), pack_h2(v1.z, v1.w));
}
static __device__ __forceinline__ void cp_async16(uint32_t saddr, const void* gaddr) {
    asm volatile("cp.async.cg.shared.global [%0], [%1], 16;"
        :: "r"(saddr), "l"(gaddr) : "memory");
}
static __device__ __forceinline__ void cp_commit() {
    asm volatile("cp.async.commit_group;" ::: "memory");
}
static __device__ __forceinline__ void cp_wait0() {
    asm volatile("cp.async.wait_group 0;" ::: "memory");
}

// ---------------------------------------------------------------------------
// Kernel 1: QKV projection, fp16 m16n8k16 + ldmatrix, register-staged
// prefetch of chunk c+1 overlapping the MMA loop of chunk c.
// Grid (NROWS/128, 3). Block 256 (8 warps). CTA tile 128x64, K-chunk 64.
// ---------------------------------------------------------------------------
#define QKC 64
#define EH 72
#define WH 72

__global__ __launch_bounds__(256)
void qkv_proj_kernel(const float* __restrict__ emb,
                     const float* __restrict__ Wq, const float* __restrict__ bq,
                     const float* __restrict__ Wk, const float* __restrict__ bk,
                     const float* __restrict__ Wv, const float* __restrict__ bv)
{
    __shared__ __align__(16) __half Es[128 * EH];   // emb tile 128x64
    __shared__ __align__(16) __half Ws[64 * WH];    // W tile [k][n]

    const int tid  = threadIdx.x;
    const int warp = tid >> 5;
    const int lane = tid & 31;
    const int rs   = warp & 3;
    const int ch   = warp >> 2;
    const int row0 = blockIdx.x * 128;
    const int mat  = blockIdx.y;

    const float* W    = (mat == 0) ? Wq : (mat == 1) ? Wk : Wv;
    const float* bias = (mat == 0) ? bq : (mat == 1) ? bk : bv;
    __half* outp      = (mat == 0) ? g_Qh : (mat == 1) ? g_Kh : g_Vh;
    const float osc   = (mat == 0) ? QSC : 1.0f;

    float acc[2][4][4];
#pragma unroll
    for (int mt = 0; mt < 2; ++mt)
#pragma unroll
        for (int n = 0; n < 4; ++n)
#pragma unroll
            for (int j = 0; j < 4; ++j) acc[mt][n][j] = 0.f;

    const uint32_t esb = smem_to_u32(Es);
    const uint32_t wsb = smem_to_u32(Ws);
    const int l8 = lane & 7;
    const int arow = l8 + ((lane >> 3) & 1) * 8;
    const int acol = ((lane >> 4) & 1) * 8;
    const int trow = l8 + ((lane >> 3) & 1) * 8;
    const int tcol = ((lane >> 4) & 1) * 8;

    // loader indices (constant)
    const int er  = tid >> 3;            // emb row within 256-thread slab (+i*32)
    const int egp = tid & 7;             // emb 8-half group
    // emb rows covered per i-step: r = (tid + i*256)>>3 -> er + i*32
    const int wr  = tid >> 3;            // W row (+i*32), rows 0..63 over 2 steps
    const int wgp = tid & 7;

    // prologue: load chunk 0 synchronously
    {
#pragma unroll
        for (int i = 0; i < 4; ++i) {
            int r = er + i * 32;
            const float* src = emb + (size_t)(row0 + r) * D_MODEL_C + egp * 8;
            float4 v0 = *reinterpret_cast<const float4*>(src);
            float4 v1 = *reinterpret_cast<const float4*>(src + 4);
            *reinterpret_cast<uint4*>(&Es[r * EH + egp * 8]) = cvt8_h(v0, v1);
        }
#pragma unroll
        for (int i = 0; i < 2; ++i) {
            int r = wr + i * 32;
            const float* src = W + (size_t)r * DK_C + wgp * 8;
            float4 v0 = *reinterpret_cast<const float4*>(src);
            float4 v1 = *reinterpret_cast<const float4*>(src + 4);
            *reinterpret_cast<uint4*>(&Ws[r * WH + wgp * 8]) = cvt8_h(v0, v1);
        }
    }
    __syncthreads();

    for (int kc = 0; kc < D_MODEL_C / QKC; ++kc) {
        // prefetch chunk kc+1 into registers (overlaps MMA below)
        float4 pe[8], pw[4];
        const bool pref = (kc + 1 < D_MODEL_C / QKC);
        if (pref) {
            const int koff = (kc + 1) * QKC;
#pragma unroll
            for (int i = 0; i < 4; ++i) {
                int r = er + i * 32;
                const float* src = emb + (size_t)(row0 + r) * D_MODEL_C + koff + egp * 8;
                pe[2 * i]     = *reinterpret_cast<const float4*>(src);
                pe[2 * i + 1] = *reinterpret_cast<const float4*>(src + 4);
            }
#pragma unroll
            for (int i = 0; i < 2; ++i) {
                int r = wr + i * 32;
                const float* src = W + (size_t)(koff + r) * DK_C + wgp * 8;
                pw[2 * i]     = *reinterpret_cast<const float4*>(src);
                pw[2 * i + 1] = *reinterpret_cast<const float4*>(src + 4);
            }
        }
        // MMA loop on current chunk in smem
#pragma unroll
        for (int ks = 0; ks < QKC / 16; ++ks) {
            uint32_t a[2][4];
#pragma unroll
            for (int mt = 0; mt < 2; ++mt)
                ldsm_x4(a[mt], esb + ((rs * 32 + mt * 16 + arow) * EH + ks * 16 + acol) * 2);
#pragma unroll
            for (int np = 0; np < 2; ++np) {
                uint32_t b[4];
                ldsm_x4_t(b, wsb + ((ks * 16 + trow) * WH + ch * 32 + np * 16 + tcol) * 2);
                mma_f16(acc[0][2 * np],     a[0], b[0], b[1]);
                mma_f16(acc[1][2 * np],     a[1], b[0], b[1]);
                mma_f16(acc[0][2 * np + 1], a[0], b[2], b[3]);
                mma_f16(acc[1][2 * np + 1], a[1], b[2], b[3]);
            }
        }
        __syncthreads();   // all warps done reading chunk kc
        if (pref) {
#pragma unroll
            for (int i = 0; i < 4; ++i) {
                int r = er + i * 32;
                *reinterpret_cast<uint4*>(&Es[r * EH + egp * 8]) =
                    cvt8_h(pe[2 * i], pe[2 * i + 1]);
            }
#pragma unroll
            for (int i = 0; i < 2; ++i) {
                int r = wr + i * 32;
                *reinterpret_cast<uint4*>(&Ws[r * WH + wgp * 8]) =
                    cvt8_h(pw[2 * i], pw[2 * i + 1]);
            }
            __syncthreads();   // chunk kc+1 ready
        }
    }
    // Epilogue: bias add, scale (Q only), fp16 stores
    const int g  = lane >> 2;
    const int cb = (lane & 3) * 2;
#pragma unroll
    for (int mt = 0; mt < 2; ++mt) {
        const int r = row0 + rs * 32 + mt * 16 + g;
#pragma unroll
        for (int n = 0; n < 4; ++n) {
            int col = ch * 32 + n * 8 + cb;
            float b0 = bias[col], b1 = bias[col + 1];
            *reinterpret_cast<__half2*>(&outp[(size_t)r * DK_C + col]) =
                __floats2half2_rn((acc[mt][n][0] + b0) * osc, (acc[mt][n][1] + b1) * osc);
            *reinterpret_cast<__half2*>(&outp[(size_t)(r + 8) * DK_C + col]) =
                __floats2half2_rn((acc[mt][n][2] + b0) * osc, (acc[mt][n][3] + b1) * osc);
        }
    }
}

// ---------------------------------------------------------------------------
// Kernel 2: flash attention, fp16 m16n8k16 + ldmatrix, split-KV (4).
// cp.async double-buffered K/V pipeline: tile t+1 loads during tile t compute.
// ---------------------------------------------------------------------------
#define ATS 72
#define KVBYTES (64 * ATS * 2)   // 9216 per tile buffer

__global__ __launch_bounds__(128)
void attn_kernel()
{
    __shared__ __align__(16) __half Kh[2][64 * ATS];
    __shared__ __align__(16) __half Vh[2][64 * ATS];
    __shared__ __align__(16) __half Ph[64 * ATS];   // Q staging, then P

    const int tid   = threadIdx.x;
    const int warp  = tid >> 5;
    const int lane  = tid & 31;
    const int b     = blockIdx.y;
    const int q0    = blockIdx.x * 64;
    const int split = blockIdx.z;
    const int t0t   = split * TILES_PER_SPLIT;

    const __half* Qg = g_Qh + ((size_t)b * S_C + q0) * DK_C;
    const __half* Kg = g_Kh + (size_t)b * S_C * DK_C;
    const __half* Vg = g_Vh + (size_t)b * S_C * DK_C;

    const uint32_t kb = smem_to_u32(Kh);
    const uint32_t vb = smem_to_u32(Vh);
    const uint32_t pb = smem_to_u32(Ph);
    const int l8 = lane & 7;
    const int arow = l8 + ((lane >> 3) & 1) * 8;
    const int acol = ((lane >> 4) & 1) * 8;
    const int brow = l8 + ((lane >> 4) & 1) * 8;
    const int bcol = ((lane >> 3) & 1) * 8;
    const int trow = l8 + ((lane >> 3) & 1) * 8;
    const int tcol = ((lane >> 4) & 1) * 8;

    const int lr  = tid >> 3;     // loader row (+i*16 over 4 steps covers 0..63)
    const int lgp = tid & 7;

    // issue cp.async for one K/V tile into buffer `bf`
    auto issue_tile = [&](int t, int bf) {
#pragma unroll
        for (int i = 0; i < 4; ++i) {
            int r = lr + i * 16;
            const __half* ks_ = Kg + ((size_t)t * 64 + r) * DK_C + lgp * 8;
            const __half* vs_ = Vg + ((size_t)t * 64 + r) * DK_C + lgp * 8;
            uint32_t off = (uint32_t)(bf * KVBYTES + (r * ATS + lgp * 8) * 2);
            cp_async16(kb + off, ks_);
            cp_async16(vb + off, vs_);
        }
        cp_commit();
    };

    // prologue: start tile 0 load, stage Q, extract fragments
    issue_tile(t0t, 0);
#pragma unroll
    for (int i = 0; i < 4; ++i) {
        int r = lr + i * 16;
        *reinterpret_cast<uint4*>(&Ph[r * ATS + lgp * 8]) =
            reinterpret_cast<const uint4*>(Qg + (size_t)r * DK_C)[lgp];
    }
    __syncthreads();
    uint32_t qf[4][4];
#pragma unroll
    for (int ks = 0; ks < 4; ++ks)
        ldsm_x4(qf[ks], pb + ((warp * 16 + arow) * ATS + ks * 16 + acol) * 2);

    float o[8][4];
#pragma unroll
    for (int n = 0; n < 8; ++n)
#pragma unroll
        for (int j = 0; j < 4; ++j) o[n][j] = 0.f;
    float m0 = -1e30f, m1 = -1e30f, l0 = 0.f, l1 = 0.f;

    const int g  = lane >> 2;
    const int ac = lane & 3;
    const int ar = warp * 16 + g;

    for (int tt = 0; tt < TILES_PER_SPLIT; ++tt) {
        const int bf = tt & 1;
        cp_wait0();          // tile tt landed (this thread's copies)
        __syncthreads();     // cross-thread visibility + all warps done with tt-1
        if (tt + 1 < TILES_PER_SPLIT) issue_tile(t0t + tt + 1, bf ^ 1);

        const uint32_t kbb = kb + bf * KVBYTES;
        const uint32_t vbb = vb + bf * KVBYTES;

        // S = Qs @ K^T (scale folded into Q; log2-domain)
        float s[8][4];
#pragma unroll
        for (int n = 0; n < 8; ++n)
#pragma unroll
            for (int j = 0; j < 4; ++j) s[n][j] = 0.f;
#pragma unroll
        for (int ks = 0; ks < 4; ++ks) {
#pragma unroll
            for (int np = 0; np < 4; ++np) {
                uint32_t bfr[4];
                ldsm_x4(bfr, kbb + ((np * 16 + brow) * ATS + ks * 16 + bcol) * 2);
                mma_f16(s[2 * np],     qf[ks], bfr[0], bfr[1]);
                mma_f16(s[2 * np + 1], qf[ks], bfr[2], bfr[3]);
            }
        }

        // Online softmax
        float mx0 = m0, mx1 = m1;
#pragma unroll
        for (int n = 0; n < 8; ++n) {
            mx0 = fmaxf(mx0, fmaxf(s[n][0], s[n][1]));
            mx1 = fmaxf(mx1, fmaxf(s[n][2], s[n][3]));
        }
        mx0 = fmaxf(mx0, __shfl_xor_sync(0xffffffffu, mx0, 1));
        mx0 = fmaxf(mx0, __shfl_xor_sync(0xffffffffu, mx0, 2));
        mx1 = fmaxf(mx1, __shfl_xor_sync(0xffffffffu, mx1, 1));
        mx1 = fmaxf(mx1, __shfl_xor_sync(0xffffffffu, mx1, 2));
        float a0 = exp2_approx(m0 - mx0);
        float a1 = exp2_approx(m1 - mx1);
        float rs0 = 0.f, rs1 = 0.f;
#pragma unroll
        for (int n = 0; n < 8; ++n) {
            s[n][0] = exp2_approx(s[n][0] - mx0);
            s[n][1] = exp2_approx(s[n][1] - mx0);
            s[n][2] = exp2_approx(s[n][2] - mx1);
            s[n][3] = exp2_approx(s[n][3] - mx1);
            rs0 += s[n][0] + s[n][1];
            rs1 += s[n][2] + s[n][3];
        }
        rs0 += __shfl_xor_sync(0xffffffffu, rs0, 1);
        rs0 += __shfl_xor_sync(0xffffffffu, rs0, 2);
        rs1 += __shfl_xor_sync(0xffffffffu, rs1, 1);
        rs1 += __shfl_xor_sync(0xffffffffu, rs1, 2);
        l0 = l0 * a0 + rs0;
        l1 = l1 * a1 + rs1;
        m0 = mx0; m1 = mx1;
#pragma unroll
        for (int n = 0; n < 8; ++n) {
            o[n][0] *= a0; o[n][1] *= a0; o[n][2] *= a1; o[n][3] *= a1;
        }

        // P -> fp16 smem (warp-private rows)
#pragma unroll
        for (int n = 0; n < 8; ++n) {
            *reinterpret_cast<uint32_t*>(&Ph[ar * ATS + n * 8 + 2 * ac]) =
                pack_h2(s[n][0], s[n][1]);
            *reinterpret_cast<uint32_t*>(&Ph[(ar + 8) * ATS + n * 8 + 2 * ac]) =
                pack_h2(s[n][2], s[n][3]);
        }
        __syncwarp();

        // O += P @ V
#pragma unroll
        for (int ks = 0; ks < 4; ++ks) {
            uint32_t afr[4];
            ldsm_x4(afr, pb + ((warp * 16 + arow) * ATS + ks * 16 + acol) * 2);
#pragma unroll
            for (int np = 0; np < 4; ++np) {
                uint32_t bfr[4];
                ldsm_x4_t(bfr, vbb + ((ks * 16 + trow) * ATS + np * 16 + tcol) * 2);
                mma_f16(o[2 * np],     afr, bfr[0], bfr[1]);
                mma_f16(o[2 * np + 1], afr, bfr[2], bfr[3]);
            }
        }
    }

    // Epilogue: unnormalized partial O + (m, l)
    float* op = g_Opart + ((size_t)split * NROWS_C + (size_t)b * S_C + q0) * DK_C;
    const int cb = ac * 2;
#pragma unroll
    for (int n = 0; n < 8; ++n) {
        int col = n * 8 + cb;
        *reinterpret_cast<float2*>(&op[(size_t)ar * DK_C + col]) =
            make_float2(o[n][0], o[n][1]);
        *reinterpret_cast<float2*>(&op[(size_t)(ar + 8) * DK_C + col]) =
            make_float2(o[n][2], o[n][3]);
    }
    if (ac == 0) {
        size_t base = (size_t)split * NROWS_C + (size_t)b * S_C + q0;
        g_m[base + ar] = m0;     g_l[base + ar] = l0;
        g_m[base + ar + 8] = m1; g_l[base + ar + 8] = l1;
    }
}

// ---------------------------------------------------------------------------
// Kernel 3: combine partials across splits.
// ---------------------------------------------------------------------------
__global__ __launch_bounds__(256)
void combine_kernel(float* __restrict__ out)
{
    int idx = blockIdx.x * 256 + threadIdx.x;
    int row = idx >> 4;
    int c4  = (idx & 15) * 4;

    float ms[NSPLIT];
    float m = -1e30f;
#pragma unroll
    for (int s = 0; s < NSPLIT; ++s) {
        ms[s] = g_m[(size_t)s * NROWS_C + row];
        m = fmaxf(m, ms[s]);
    }
    float l = 0.f;
    float ox = 0.f, oy = 0.f, oz = 0.f, ow = 0.f;
#pragma unroll
    for (int s = 0; s < NSPLIT; ++s) {
        float w = exp2_approx(ms[s] - m);
        l += g_l[(size_t)s * NROWS_C + row] * w;
        float4 p = *reinterpret_cast<const float4*>(
            &g_Opart[((size_t)s * NROWS_C + row) * DK_C + c4]);
        ox += p.x * w; oy += p.y * w; oz += p.z * w; ow += p.w * w;
    }
    float inv = 1.f / l;
    *reinterpret_cast<float4*>(&out[(size_t)row * DK_C + c4]) =
        make_float4(ox * inv, oy * inv, oz * inv, ow * inv);
}

// ---------------------------------------------------------------------------
extern "C" void kernel_launch(void* const* d_in, const int* in_sizes, int n_in,
                              void* d_out, int out_size) {
    (void)in_sizes; (void)n_in; (void)out_size;
    const float* emb = (const float*)d_in[0];
    const float* Wq  = (const float*)d_in[1];
    const float* bq  = (const float*)d_in[2];
    const float* Wk  = (const float*)d_in[3];
    const float* bk  = (const float*)d_in[4];
    const float* Wv  = (const float*)d_in[5];
    const float* bv  = (const float*)d_in[6];

    dim3 qgrid(NROWS_C / 128, 3);
    qkv_proj_kernel<<<qgrid, 256>>>(emb, Wq, bq, Wk, bk, Wv, bv);
    dim3 agrid(S_C / 64, B_C, NSPLIT);
    attn_kernel<<<agrid, 128>>>();
    combine_kernel<<<(NROWS_C * 16) / 256, 256>>>((float*)d_out);
}